// round 11
// baseline (speedup 1.0000x reference)
#include <cuda_runtime.h>
#include <cuda_bf16.h>
#include <math.h>
#include <stdint.h>

// Problem constants
#define SQ   2048
#define HID  1024
#define DH   64
#define NHB  16
#define BHSD (NHB*SQ*DH)

// ---------------- scratch (static device memory; no allocation) ----------------
__device__ float g_V   [BHSD];
__device__ float g_LV  [BHSD];
__device__ float g_LQ  [BHSD];
__device__ float g_LK1 [BHSD];
__device__ float g_Mm  [NHB*64*64];
// packed bf16 hi/lo pairs: .x = (hi[d],hi[d+1]), .y = (lo[d],lo[d+1])
// plane = branch*16 + (b*8+h): 0-15 global, 16-31 local
__device__ __align__(16) uint2 g_Qp [32*SQ*(DH/2)];   // [plane][s][dpair]
__device__ __align__(16) uint2 g_Kp [32*SQ*(DH/2)];   // [plane][s][dpair]
__device__ __align__(16) uint2 g_Vtp[32*DH*(SQ/2)];   // [plane][d][spair]

struct ProjW {
    const float* w[7];
    const float* b[7];
    const float* w2;   // wlv2 (summed into pz==6)
    const float* b2;   // blv2
};

// ---------------- helpers ----------------
__device__ __forceinline__ float tf32_rna(float x) {
    uint32_t r; asm("cvt.rna.tf32.f32 %0, %1;" : "=r"(r) : "f"(x));
    return __uint_as_float(r);
}
__device__ __forceinline__ void mma8(float c[4],
        float a0, float a1, float a2, float a3, float b0, float b1) {
    uint32_t A0 = __float_as_uint(a0), A1 = __float_as_uint(a1),
             A2 = __float_as_uint(a2), A3 = __float_as_uint(a3),
             B0 = __float_as_uint(b0), B1 = __float_as_uint(b1);
    asm volatile(
        "mma.sync.aligned.m16n8k8.row.col.f32.tf32.tf32.f32 "
        "{%0,%1,%2,%3}, {%4,%5,%6,%7}, {%8,%9}, {%0,%1,%2,%3};"
        : "+f"(c[0]), "+f"(c[1]), "+f"(c[2]), "+f"(c[3])
        : "r"(A0), "r"(A1), "r"(A2), "r"(A3), "r"(B0), "r"(B1));
}
// bf16 m16n8k16 row.col, fp32 accumulate
__device__ __forceinline__ void mma16(float c[4], const uint32_t a[4],
                                      uint32_t b0, uint32_t b1) {
    asm volatile(
        "mma.sync.aligned.m16n8k16.row.col.f32.bf16.bf16.f32 "
        "{%0,%1,%2,%3}, {%4,%5,%6,%7}, {%8,%9}, {%0,%1,%2,%3};"
        : "+f"(c[0]), "+f"(c[1]), "+f"(c[2]), "+f"(c[3])
        : "r"(a[0]), "r"(a[1]), "r"(a[2]), "r"(a[3]), "r"(b0), "r"(b1));
}
__device__ __forceinline__ void cp16(uint32_t dst, const void* src) {
    asm volatile("cp.async.cg.shared.global [%0], [%1], 16;\n" :: "r"(dst), "l"(src));
}
__device__ __forceinline__ uint32_t pk2(__nv_bfloat16 a, __nv_bfloat16 b) {
    uint16_t xa = *reinterpret_cast<uint16_t*>(&a);
    uint16_t xb = *reinterpret_cast<uint16_t*>(&b);
    return (uint32_t)xa | ((uint32_t)xb << 16);
}
__device__ __forceinline__ uint2 pk_pair(float v0, float v1) {
    __nv_bfloat16 h0 = __float2bfloat16_rn(v0), h1 = __float2bfloat16_rn(v1);
    float l0 = v0 - __bfloat162float(h0), l1 = v1 - __bfloat162float(h1);
    return make_uint2(pk2(h0, h1),
                      pk2(__float2bfloat16_rn(l0), __float2bfloat16_rn(l1)));
}

// ---------------- kernel 1: projection GEMM (3xTF32 legacy mma) ----------------
// pz: 0=Q->packed (x0.125), 1=K->packed, 2=V fp32, 3=LQ fp32, 4=LK1 fp32,
//     5=LK2->packed plane 16+, 6=LV fp32 (wlv1+wlv2 summed inline)
#define XS_STRIDE 18
#define WS_STRIDE 132

__global__ __launch_bounds__(256) void proj_tc(const float* __restrict__ X, ProjW args) {
    const int pz = blockIdx.z;
    const float* __restrict__ W  = args.w[pz];
    const float* __restrict__ Bv = args.b[pz];
    const float* __restrict__ W2 = args.w2;
    const float* __restrict__ B2 = args.b2;

    const int n0 = blockIdx.x * 128;
    const int m0 = blockIdx.y * 128;

    __shared__ float2 Xs[128 * XS_STRIDE];
    __shared__ float2 Ws[16 * WS_STRIDE];

    const int tid  = threadIdx.x;
    const int w    = tid >> 5;
    const int lane = tid & 31;
    const int g    = lane >> 2;
    const int tg   = lane & 3;
    const int wm   = w & 3;
    const int wn   = w >> 2;

    float acc[2][8][4];
    #pragma unroll
    for (int mt = 0; mt < 2; mt++)
        #pragma unroll
        for (int n = 0; n < 8; n++)
            #pragma unroll
            for (int q = 0; q < 4; q++) acc[mt][n][q] = 0.f;

    float4 xr[2], wr[2];
    auto loadX = [&](int kb) {
        #pragma unroll
        for (int t = 0; t < 2; t++) {
            int i2 = tid + 256*t; int r = i2 >> 2, c = i2 & 3;
            xr[t] = *(const float4*)&X[(size_t)(m0 + r) * HID + kb + 4*c];
        }
    };
    auto loadW = [&](int kb) {
        #pragma unroll
        for (int t = 0; t < 2; t++) {
            int i2 = tid + 256*t; int r = i2 >> 5, c = i2 & 31;
            wr[t] = *(const float4*)&W[(size_t)(kb + r) * 512 + n0 + 4*c];
            if (pz == 6) {
                float4 x2 = *(const float4*)&W2[(size_t)(kb + r) * 512 + n0 + 4*c];
                wr[t].x += x2.x; wr[t].y += x2.y; wr[t].z += x2.z; wr[t].w += x2.w;
            }
        }
    };

    loadX(0); loadW(0);

    for (int kb = 0; kb < HID; kb += 16) {
        __syncthreads();
        #pragma unroll
        for (int t = 0; t < 2; t++) {
            int i2 = tid + 256*t; int r = i2 >> 2, c = i2 & 3;
            float4 x = xr[t];
            float h0 = tf32_rna(x.x), h1 = tf32_rna(x.y), h2 = tf32_rna(x.z), h3 = tf32_rna(x.w);
            float4* p = (float4*)&Xs[r * XS_STRIDE + 4*c];
            p[0] = make_float4(h0, x.x - h0, h1, x.y - h1);
            p[1] = make_float4(h2, x.z - h2, h3, x.w - h3);
        }
        #pragma unroll
        for (int t = 0; t < 2; t++) {
            int i2 = tid + 256*t; int r = i2 >> 5, c = i2 & 31;
            float4 x = wr[t];
            float h0 = tf32_rna(x.x), h1 = tf32_rna(x.y), h2 = tf32_rna(x.z), h3 = tf32_rna(x.w);
            float4* p = (float4*)&Ws[r * WS_STRIDE + 4*c];
            p[0] = make_float4(h0, x.x - h0, h1, x.y - h1);
            p[1] = make_float4(h2, x.z - h2, h3, x.w - h3);
        }
        if (kb + 16 < HID) { loadX(kb + 16); loadW(kb + 16); }
        __syncthreads();

        #pragma unroll
        for (int kk = 0; kk < 2; kk++) {
            float2 a[2][4];
            #pragma unroll
            for (int mt = 0; mt < 2; mt++) {
                int r = 32*wm + 16*mt;
                a[mt][0] = Xs[(r + g    ) * XS_STRIDE + 8*kk + tg    ];
                a[mt][1] = Xs[(r + g + 8) * XS_STRIDE + 8*kk + tg    ];
                a[mt][2] = Xs[(r + g    ) * XS_STRIDE + 8*kk + tg + 4];
                a[mt][3] = Xs[(r + g + 8) * XS_STRIDE + 8*kk + tg + 4];
            }
            #pragma unroll
            for (int n = 0; n < 8; n++) {
                float2 b0 = Ws[(8*kk + tg    ) * WS_STRIDE + 64*wn + 8*n + g];
                float2 b1 = Ws[(8*kk + tg + 4) * WS_STRIDE + 64*wn + 8*n + g];
                #pragma unroll
                for (int mt = 0; mt < 2; mt++) {
                    mma8(acc[mt][n], a[mt][0].x, a[mt][1].x, a[mt][2].x, a[mt][3].x, b0.x, b1.x);
                    mma8(acc[mt][n], a[mt][0].x, a[mt][1].x, a[mt][2].x, a[mt][3].x, b0.y, b1.y);
                    mma8(acc[mt][n], a[mt][0].y, a[mt][1].y, a[mt][2].y, a[mt][3].y, b0.x, b1.x);
                }
            }
        }
    }

    // epilogue
    #pragma unroll
    for (int mt = 0; mt < 2; mt++) {
        #pragma unroll
        for (int n = 0; n < 8; n++) {
            int col = 64*wn + 8*n + 2*tg;
            int hh  = (n0 + col) >> 6;
            int d   = (n0 + col) & 63;      // even
            float b0 = Bv[n0 + col], b1 = Bv[n0 + col + 1];
            if (pz == 6) { b0 += B2[n0 + col]; b1 += B2[n0 + col + 1]; }
            #pragma unroll
            for (int half = 0; half < 2; half++) {
                int m = m0 + 32*wm + 16*mt + g + 8*half;
                int bb = m >> 11, s = m & 2047;
                float v0 = acc[mt][n][2*half + 0] + b0;
                float v1 = acc[mt][n][2*half + 1] + b1;
                int cidx = bb*8 + hh;
                if (pz == 0) {
                    g_Qp[((size_t)cidx * SQ + s) * (DH/2) + (d>>1)] =
                        pk_pair(v0 * 0.125f, v1 * 0.125f);
                } else if (pz == 1) {
                    g_Kp[((size_t)cidx * SQ + s) * (DH/2) + (d>>1)] = pk_pair(v0, v1);
                } else if (pz == 5) {
                    g_Kp[((size_t)(16 + cidx) * SQ + s) * (DH/2) + (d>>1)] = pk_pair(v0, v1);
                } else {
                    float* Out = (pz == 2) ? g_V : (pz == 3) ? g_LQ
                               : (pz == 4) ? g_LK1 : g_LV;
                    *(float2*)&Out[((size_t)cidx * SQ + s) * DH + d] = make_float2(v0, v1);
                }
            }
        }
    }
}

// ---------------- kernel 2: aux = gram (blocks 0-15) + vtrans (blocks 16-1039) ----------------
__global__ __launch_bounds__(256) void aux_kernel() {
    __shared__ float T[64][65];
    const int tid = threadIdx.x;
    const int bid = blockIdx.x;

    if (bid < 16) {
        // ---- Gram matrix G = LK1^T LK1 for bh = bid ----
        const int bh = bid;
        const float* __restrict__ P = g_LK1 + (size_t)bh * SQ * DH;
        const int ty = tid >> 4, tx = tid & 15;

        float acc[4][4];
        #pragma unroll
        for (int i = 0; i < 4; i++)
            #pragma unroll
            for (int j = 0; j < 4; j++) acc[i][j] = 0.f;

        for (int s0 = 0; s0 < SQ; s0 += 32) {
            #pragma unroll
            for (int t = 0; t < 2; t++) {
                int idx = tid + t * 256;
                int r = idx >> 4, c = idx & 15;
                float4 v = *(const float4*)&P[(size_t)(s0 + r) * DH + 4*c];
                T[r][4*c+0] = v.x; T[r][4*c+1] = v.y; T[r][4*c+2] = v.z; T[r][4*c+3] = v.w;
            }
            __syncthreads();
            #pragma unroll 8
            for (int ss = 0; ss < 32; ss++) {
                float a_[4], b_[4];
                #pragma unroll
                for (int i = 0; i < 4; i++) a_[i] = T[ss][4*ty + i];
                #pragma unroll
                for (int j = 0; j < 4; j++) b_[j] = T[ss][4*tx + j];
                #pragma unroll
                for (int i = 0; i < 4; i++)
                    #pragma unroll
                    for (int j = 0; j < 4; j++) acc[i][j] += a_[i] * b_[j];
            }
            __syncthreads();
        }
        #pragma unroll
        for (int i = 0; i < 4; i++)
            #pragma unroll
            for (int j = 0; j < 4; j++)
                g_Mm[bh*4096 + (4*ty + i)*64 + (4*tx + j)] = acc[i][j];
    } else {
        // ---- V transpose -> packed [plane][d][spair] ----
        const int vb = bid - 16;
        const int plane = vb >> 5;
        const int s0 = (vb & 31) * 64;
        const float* __restrict__ src = (plane < 16)
            ? g_V  + (size_t)plane * SQ * DH
            : g_LV + (size_t)(plane - 16) * SQ * DH;
        #pragma unroll
        for (int t = 0; t < 16; t++) {
            int idx = tid + 256*t;
            int sl = idx >> 6, d = idx & 63;
            T[d][sl] = src[(size_t)(s0 + sl) * DH + d];
        }
        __syncthreads();
        uint2* dst = g_Vtp + (size_t)plane * DH * (SQ/2);
        #pragma unroll
        for (int t = 0; t < 8; t++) {
            int idx = tid + 256*t;
            int d = idx >> 5, sp = idx & 31;
            dst[(size_t)d * (SQ/2) + (s0 >> 1) + sp] = pk_pair(T[d][2*sp], T[d][2*sp + 1]);
        }
    }
}

// ---------------- kernel 3: LQ2 = (LQ @ G) * 0.125 -> packed plane 16+bh ----------------
__global__ __launch_bounds__(256) void lqx_kernel() {
    const int bh = blockIdx.y;
    const int r0 = blockIdx.x * 64;
    const float* __restrict__ Qp = g_LQ + (size_t)bh * SQ * DH;
    const float* __restrict__ Mp = g_Mm + bh * 4096;

    __shared__ float Msm[64*65];
    __shared__ float Qt[64*65];

    const int tid = threadIdx.x;

    #pragma unroll
    for (int t = 0; t < 4; t++) {
        int idx = tid + t * 256;
        int r = idx >> 4, c = idx & 15;
        float4 mv = *(const float4*)&Mp[r*64 + 4*c];
        Msm[r*65 + 4*c+0] = mv.x; Msm[r*65 + 4*c+1] = mv.y;
        Msm[r*65 + 4*c+2] = mv.z; Msm[r*65 + 4*c+3] = mv.w;
        float4 qv = *(const float4*)&Qp[(size_t)(r0 + r) * DH + 4*c];
        Qt[r*65 + 4*c+0] = qv.x; Qt[r*65 + 4*c+1] = qv.y;
        Qt[r*65 + 4*c+2] = qv.z; Qt[r*65 + 4*c+3] = qv.w;
    }
    __syncthreads();

    const int ty = tid >> 5;
    const int tx = tid & 31;

    float acc[8][2];
    #pragma unroll
    for (int a = 0; a < 8; a++) { acc[a][0] = 0.f; acc[a][1] = 0.f; }

    #pragma unroll 4
    for (int k = 0; k < 64; k++) {
        float mb0 = Msm[k*65 + 2*tx], mb1 = Msm[k*65 + 2*tx + 1];
        #pragma unroll
        for (int a = 0; a < 8; a++) {
            float qa = Qt[(ty + 8*a)*65 + k];
            acc[a][0] += qa * mb0;
            acc[a][1] += qa * mb1;
        }
    }

    const int plane = 16 + bh;
    #pragma unroll
    for (int a = 0; a < 8; a++) {
        int row = r0 + ty + 8*a;
        g_Qp[((size_t)plane * SQ + row) * (DH/2) + tx] =
            pk_pair(acc[a][0] * 0.125f, acc[a][1] * 0.125f);
    }
}

// ---------------- kernel 4: flash attention, bf16 m16n8k16, BR=128 / 8 warps ----------------
#define KSTR 36   // uint2 per staged row

__global__ __launch_bounds__(256, 1) void flash_bf(const float* __restrict__ mask,
                                                   float* __restrict__ out) {
    extern __shared__ uint2 smem2[];
    uint2* Kb0 = smem2;                // 64*KSTR
    uint2* Kb1 = Kb0 + 64*KSTR;
    uint2* Vb0 = Kb1 + 64*KSTR;
    uint2* Vb1 = Vb0 + 64*KSTR;

    const int rt = blockIdx.x;          // 128-row tile 0..15
    const int plane = blockIdx.y;
    const int branch = plane >> 4;
    const int cidx = plane & 15;
    const int bb = cidx >> 3;
    const int h  = cidx & 7;
    const int ho = branch ? (8 + h) : h;
    const bool domask = (branch == 0);

    const uint2* Qp  = g_Qp  + (size_t)plane * SQ * (DH/2);
    const uint2* Kp  = g_Kp  + (size_t)plane * SQ * (DH/2);
    const uint2* Vtp = g_Vtp + (size_t)plane * DH * (SQ/2);

    const int tid  = threadIdx.x;
    const int lane = tid & 31;
    const int g    = lane >> 2;
    const int tg   = lane & 3;
    const int r0   = 16 * (tid >> 5);   // warp row base 0..112

    const uint32_t kb0 = (uint32_t)__cvta_generic_to_shared(Kb0);
    const uint32_t kb1 = (uint32_t)__cvta_generic_to_shared(Kb1);
    const uint32_t vb0 = (uint32_t)__cvta_generic_to_shared(Vb0);
    const uint32_t vb1 = (uint32_t)__cvta_generic_to_shared(Vb1);

    auto stage = [&](int kt, int buf) {
        uint32_t kb = buf ? kb1 : kb0;
        uint32_t vb = buf ? vb1 : vb0;
        #pragma unroll
        for (int t = 0; t < 4; t++) {
            int idx = tid + 256*t;          // 0..1023
            int r = idx >> 4, c = idx & 15;
            cp16(kb + (uint32_t)(r*KSTR*8 + c*16),
                 Kp + (size_t)(kt*64 + r) * (DH/2) + 2*c);
            cp16(vb + (uint32_t)(r*KSTR*8 + c*16),
                 Vtp + (size_t)r * (SQ/2) + kt*32 + 2*c);
        }
        asm volatile("cp.async.commit_group;\n");
    };

    // ---- Q fragments (packed hi/lo, register-resident) ----
    uint32_t qh[4][4], ql[4][4];
    #pragma unroll
    for (int kk = 0; kk < 4; kk++) {
        const uint2* qb = Qp + (size_t)(rt*128) * (DH/2);
        uint2 q00 = qb[(size_t)(r0 + g    ) * (DH/2) + 8*kk + tg    ];
        uint2 q10 = qb[(size_t)(r0 + g + 8) * (DH/2) + 8*kk + tg    ];
        uint2 q01 = qb[(size_t)(r0 + g    ) * (DH/2) + 8*kk + tg + 4];
        uint2 q11 = qb[(size_t)(r0 + g + 8) * (DH/2) + 8*kk + tg + 4];
        qh[kk][0] = q00.x; qh[kk][1] = q10.x; qh[kk][2] = q01.x; qh[kk][3] = q11.x;
        ql[kk][0] = q00.y; ql[kk][1] = q10.y; ql[kk][2] = q01.y; ql[kk][3] = q11.y;
    }

    float o[8][4];
    #pragma unroll
    for (int n = 0; n < 8; n++)
        #pragma unroll
        for (int q = 0; q < 4; q++) o[n][q] = 0.f;
    float m0r = -3.0e38f, m1r = -3.0e38f, l0r = 0.f, l1r = 0.f;

    stage(0, 0);

    for (int kt = 0; kt < 32; kt++) {
        if (kt + 1 < 32) {
            stage(kt + 1, (kt + 1) & 1);
            asm volatile("cp.async.wait_group 1;\n");
        } else {
            asm volatile("cp.async.wait_group 0;\n");
        }
        __syncthreads();
        const uint2* Ks = (kt & 1) ? Kb1 : Kb0;
        const uint2* Vs = (kt & 1) ? Vb1 : Vb0;

        // ---- S = Q K^T (3-term bf16-pair) ----
        float sv[8][4];
        #pragma unroll
        for (int n = 0; n < 8; n++)
            #pragma unroll
            for (int q = 0; q < 4; q++) sv[n][q] = 0.f;

        #pragma unroll
        for (int kk = 0; kk < 4; kk++) {
            #pragma unroll
            for (int n = 0; n < 8; n++) {
                uint2 b0 = Ks[(8*n + g) * KSTR + 8*kk + tg    ];
                uint2 b1 = Ks[(8*n + g) * KSTR + 8*kk + tg + 4];
                mma16(sv[n], qh[kk], b0.x, b1.x);
                mma16(sv[n], qh[kk], b0.y, b1.y);
                mma16(sv[n], ql[kk], b0.x, b1.x);
            }
        }

        if (domask) {
            #pragma unroll
            for (int n = 0; n < 8; n++) {
                float2 mm = __ldg((const float2*)&mask[(size_t)bb * SQ + kt*64 + 8*n + 2*tg]);
                sv[n][0] += mm.x; sv[n][1] += mm.y;
                sv[n][2] += mm.x; sv[n][3] += mm.y;
            }
        }

        // ---- online softmax (rows g and g+8; 4-lane groups share a row) ----
        float mt0 = sv[0][0], mt1 = sv[0][2];
        #pragma unroll
        for (int n = 0; n < 8; n++) {
            mt0 = fmaxf(mt0, fmaxf(sv[n][0], sv[n][1]));
            mt1 = fmaxf(mt1, fmaxf(sv[n][2], sv[n][3]));
        }
        mt0 = fmaxf(mt0, __shfl_xor_sync(0xffffffffu, mt0, 1));
        mt0 = fmaxf(mt0, __shfl_xor_sync(0xffffffffu, mt0, 2));
        mt1 = fmaxf(mt1, __shfl_xor_sync(0xffffffffu, mt1, 1));
        mt1 = fmaxf(mt1, __shfl_xor_sync(0xffffffffu, mt1, 2));

        float mn0 = fmaxf(m0r, mt0), mn1 = fmaxf(m1r, mt1);
        float c0 = __expf(m0r - mn0), c1 = __expf(m1r - mn1);
        float s0 = 0.f, s1 = 0.f;
        #pragma unroll
        for (int n = 0; n < 8; n++) {
            sv[n][0] = __expf(sv[n][0] - mn0); s0 += sv[n][0];
            sv[n][1] = __expf(sv[n][1] - mn0); s0 += sv[n][1];
            sv[n][2] = __expf(sv[n][2] - mn1); s1 += sv[n][2];
            sv[n][3] = __expf(sv[n][3] - mn1); s1 += sv[n][3];
        }
        s0 += __shfl_xor_sync(0xffffffffu, s0, 1);
        s0 += __shfl_xor_sync(0xffffffffu, s0, 2);
        s1 += __shfl_xor_sync(0xffffffffu, s1, 1);
        s1 += __shfl_xor_sync(0xffffffffu, s1, 2);
        l0r = l0r * c0 + s0; m0r = mn0;
        l1r = l1r * c1 + s1; m1r = mn1;
        #pragma unroll
        for (int n = 0; n < 8; n++) {
            o[n][0] *= c0; o[n][1] *= c0;
            o[n][2] *= c1; o[n][3] *= c1;
        }

        // ---- pack P into bf16 hi/lo A-fragments (pure local, no shuffles) ----
        uint32_t php[8][2], plp[8][2];
        #pragma unroll
        for (int n = 0; n < 8; n++) {
            __nv_bfloat16 h0 = __float2bfloat16_rn(sv[n][0]);
            __nv_bfloat16 h1 = __float2bfloat16_rn(sv[n][1]);
            __nv_bfloat16 h2 = __float2bfloat16_rn(sv[n][2]);
            __nv_bfloat16 h3 = __float2bfloat16_rn(sv[n][3]);
            php[n][0] = pk2(h0, h1);
            php[n][1] = pk2(h2, h3);
            float l0 = sv[n][0] - __bfloat162float(h0);
            float l1 = sv[n][1] - __bfloat162float(h1);
            float l2 = sv[n][2] - __bfloat162float(h2);
            float l3 = sv[n][3] - __bfloat162float(h3);
            plp[n][0] = pk2(__float2bfloat16_rn(l0), __float2bfloat16_rn(l1));
            plp[n][1] = pk2(__float2bfloat16_rn(l2), __float2bfloat16_rn(l3));
        }

        // ---- O += P V (3-term bf16-pair) ----
        #pragma unroll
        for (int c = 0; c < 4; c++) {
            uint32_t ah[4] = { php[2*c][0], php[2*c][1], php[2*c+1][0], php[2*c+1][1] };
            uint32_t al[4] = { plp[2*c][0], plp[2*c][1], plp[2*c+1][0], plp[2*c+1][1] };
            #pragma unroll
            for (int n = 0; n < 8; n++) {
                uint2 b0 = Vs[(8*n + g) * KSTR + 8*c + tg    ];
                uint2 b1 = Vs[(8*n + g) * KSTR + 8*c + tg + 4];
                mma16(o[n], ah, b0.x, b1.x);
                mma16(o[n], ah, b0.y, b1.y);
                mma16(o[n], al, b0.x, b1.x);
            }
        }
        __syncthreads();
    }

    // ---- epilogue ----
    float inv0 = 1.0f / l0r, inv1 = 1.0f / l1r;
    int s0row = rt*128 + r0 + g;
    int s1row = s0row + 8;
    #pragma unroll
    for (int n = 0; n < 8; n++) {
        int col = 8*n + 2*tg;
        *(float2*)&out[(size_t)(bb * SQ + s0row) * HID + ho*64 + col] =
            make_float2(o[n][0] * inv0, o[n][1] * inv0);
        *(float2*)&out[(size_t)(bb * SQ + s1row) * HID + ho*64 + col] =
            make_float2(o[n][2] * inv1, o[n][3] * inv1);
    }
}

// ---------------- host ----------------
extern "C" void kernel_launch(void* const* d_in, const int* in_sizes, int n_in,
                              void* d_out, int out_size) {
    const float* X    = (const float*)d_in[0];
    const float* mask = (const float*)d_in[1];

    ProjW pw;
    pw.w[0] = (const float*)d_in[2];  pw.b[0] = (const float*)d_in[3];   // wq, bq
    pw.w[1] = (const float*)d_in[4];  pw.b[1] = (const float*)d_in[5];   // wk, bk
    pw.w[2] = (const float*)d_in[6];  pw.b[2] = (const float*)d_in[7];   // wv, bv
    pw.w[3] = (const float*)d_in[8];  pw.b[3] = (const float*)d_in[9];   // wlq
    pw.w[4] = (const float*)d_in[10]; pw.b[4] = (const float*)d_in[11];  // wlk1
    pw.w[5] = (const float*)d_in[12]; pw.b[5] = (const float*)d_in[13];  // wlk2
    pw.w[6] = (const float*)d_in[14]; pw.b[6] = (const float*)d_in[15];  // wlv1, blv1
    pw.w2   = (const float*)d_in[16]; pw.b2   = (const float*)d_in[17];  // wlv2, blv2

    // Launch order matters: flash must be the 4th visible launch (ncu capture slot).
    proj_tc<<<dim3(4, 32, 7), 256>>>(X, pw);          // 1
    aux_kernel<<<1040, 256>>>();                      // 2 (gram + vtrans)
    lqx_kernel<<<dim3(32, 16), 256>>>();              // 3

    const int smem = 4 * 64 * KSTR * sizeof(uint2);   // 73,728 B
    cudaFuncSetAttribute(flash_bf, cudaFuncAttributeMaxDynamicSharedMemorySize, smem);
    flash_bf<<<dim3(16, 32), 256, smem>>>(mask, (float*)d_out);   // 4
}

// round 12
// speedup vs baseline: 1.6747x; 1.6747x over previous
#include <cuda_runtime.h>
#include <cuda_bf16.h>
#include <math.h>
#include <stdint.h>

// Problem constants
#define SQ   2048
#define HID  1024
#define DH   64
#define NHB  16
#define BHSD (NHB*SQ*DH)

// ---------------- scratch (static device memory; no allocation) ----------------
__device__ float g_V   [BHSD];
__device__ float g_LV  [BHSD];
__device__ float g_LQ  [BHSD];
__device__ float g_LK1 [BHSD];
__device__ float g_Mm  [NHB*64*64];
__device__ float g_wsum[HID*512];
__device__ float g_bsum[512];
// packed bf16 hi/lo pairs (.x = hi pair, .y = lo pair)
__device__ __align__(16) uint2 g_Qp [32*SQ*(DH/2)];   // [plane][s][dpair]
__device__ __align__(16) uint2 g_Kp [32*SQ*(DH/2)];   // [plane][s][dpair]
__device__ __align__(16) uint2 g_Vtp[32*DH*(SQ/2)];   // [plane][d][spair]
__device__ __align__(16) uint2 g_Xp [4096*512];       // [m][kpair]
__device__ __align__(16) uint2 g_Wtp[7*512*512];      // [pz][n][kpair]

struct ProjW {
    const float* w[7];
    const float* b[7];
};

// ---------------- helpers ----------------
__device__ __forceinline__ void mma16(float c[4], const uint32_t a[4],
                                      uint32_t b0, uint32_t b1) {
    asm volatile(
        "mma.sync.aligned.m16n8k16.row.col.f32.bf16.bf16.f32 "
        "{%0,%1,%2,%3}, {%4,%5,%6,%7}, {%8,%9}, {%0,%1,%2,%3};"
        : "+f"(c[0]), "+f"(c[1]), "+f"(c[2]), "+f"(c[3])
        : "r"(a[0]), "r"(a[1]), "r"(a[2]), "r"(a[3]), "r"(b0), "r"(b1));
}
__device__ __forceinline__ void cp16(uint32_t dst, const void* src) {
    asm volatile("cp.async.cg.shared.global [%0], [%1], 16;\n" :: "r"(dst), "l"(src));
}
__device__ __forceinline__ uint32_t pk2(__nv_bfloat16 a, __nv_bfloat16 b) {
    uint16_t xa = *reinterpret_cast<uint16_t*>(&a);
    uint16_t xb = *reinterpret_cast<uint16_t*>(&b);
    return (uint32_t)xa | ((uint32_t)xb << 16);
}
__device__ __forceinline__ uint2 pk_pair(float v0, float v1) {
    __nv_bfloat16 h0 = __float2bfloat16_rn(v0), h1 = __float2bfloat16_rn(v1);
    float l0 = v0 - __bfloat162float(h0), l1 = v1 - __bfloat162float(h1);
    return make_uint2(pk2(h0, h1),
                      pk2(__float2bfloat16_rn(l0), __float2bfloat16_rn(l1)));
}

// ---------------- kernel 1: fold wlv1+wlv2 ----------------
__global__ void sum_lv_weights(const float* __restrict__ w1, const float* __restrict__ w2,
                               const float* __restrict__ b1, const float* __restrict__ b2) {
    int i = blockIdx.x * blockDim.x + threadIdx.x;
    if (i < HID*512) g_wsum[i] = w1[i] + w2[i];
    if (i < 512)     g_bsum[i] = b1[i] + b2[i];
}

// ---------------- kernel 2: split X into packed bf16 pairs ----------------
__global__ __launch_bounds__(256) void split_x(const float* __restrict__ X) {
    int idx = blockIdx.x * 256 + threadIdx.x;       // pair index, 4096*512 total
    float2 v = *(const float2*)&X[(size_t)idx * 2];
    g_Xp[idx] = pk_pair(v.x, v.y);
}

// ---------------- kernel 3: split + transpose W -> g_Wtp[pz][n][kpair] ----------------
__global__ __launch_bounds__(256) void split_w(ProjW args) {
    const int pz = blockIdx.z;
    const int n0 = blockIdx.x * 64;
    const int k0 = blockIdx.y * 64;
    const float* __restrict__ W = (pz == 6) ? g_wsum : args.w[pz];

    __shared__ float T[64][65];
    const int tid = threadIdx.x;
    #pragma unroll
    for (int t = 0; t < 16; t++) {
        int idx = tid + 256*t;          // 0..4095
        int kk = idx >> 6, nn = idx & 63;
        T[kk][nn] = W[(size_t)(k0 + kk) * 512 + n0 + nn];
    }
    __syncthreads();
    #pragma unroll
    for (int t = 0; t < 8; t++) {
        int idx = tid + 256*t;          // 0..2047 = 64n x 32kp
        int nn = idx >> 5, kp = idx & 31;
        g_Wtp[((size_t)pz * 512 + n0 + nn) * 512 + (k0 >> 1) + kp] =
            pk_pair(T[2*kp][nn], T[2*kp + 1][nn]);
    }
}

// ---------------- kernel 4: projection GEMM, bf16-pair mma16, cp.async ----------------
// out[m, n0+..] for one head-block; pz: 0=Q->packed(x0.125), 1=K->packed, 2=V fp32,
// 3=LQ fp32, 4=LK1 fp32, 5=LK2->packed plane16+, 6=LV fp32
#define PXS 20   // uint2 stride, X tile rows (16 pairs + 4 pad)
#define PWS 20

__global__ __launch_bounds__(256, 2) void proj_bf(ProjW args) {
    extern __shared__ uint2 psm[];
    // buffers: X0 [128*PXS], W0 [64*PWS], X1, W1
    const int XOFF = 128*PXS, WSZ = 64*PWS;

    const int pz = blockIdx.z;
    const int n0 = blockIdx.x * 64;
    const int m0 = blockIdx.y * 128;
    const float* __restrict__ Bv = (pz == 6) ? g_bsum : args.b[pz];

    const uint2* __restrict__ Xp  = g_Xp + (size_t)m0 * 512;
    const uint2* __restrict__ Wtp = g_Wtp + ((size_t)pz * 512 + n0) * 512;

    const int tid  = threadIdx.x;
    const int lane = tid & 31;
    const int g    = lane >> 2;
    const int tg   = lane & 3;
    const int r0   = 16 * (tid >> 5);   // warp row base

    const uint32_t sb = (uint32_t)__cvta_generic_to_shared(psm);

    auto stage = [&](int kt, int buf) {
        uint32_t xb = sb + (uint32_t)(buf * (XOFF + WSZ)) * 8u;
        uint32_t wb = xb + (uint32_t)XOFF * 8u;
        #pragma unroll
        for (int t = 0; t < 4; t++) {
            int idx = tid + 256*t;          // 0..1023
            int r = idx >> 3, c = idx & 7;
            cp16(xb + (uint32_t)(r*PXS + 2*c)*8u, Xp + (size_t)r*512 + kt*16 + 2*c);
        }
        #pragma unroll
        for (int t = 0; t < 2; t++) {
            int idx = tid + 256*t;          // 0..511
            int r = idx >> 3, c = idx & 7;
            cp16(wb + (uint32_t)(r*PWS + 2*c)*8u, Wtp + (size_t)r*512 + kt*16 + 2*c);
        }
        asm volatile("cp.async.commit_group;\n");
    };

    float acc[8][4];
    #pragma unroll
    for (int n = 0; n < 8; n++)
        #pragma unroll
        for (int q = 0; q < 4; q++) acc[n][q] = 0.f;

    stage(0, 0);

    for (int kt = 0; kt < 32; kt++) {
        if (kt + 1 < 32) {
            stage(kt + 1, (kt + 1) & 1);
            asm volatile("cp.async.wait_group 1;\n");
        } else {
            asm volatile("cp.async.wait_group 0;\n");
        }
        __syncthreads();
        const uint2* Xs = psm + (kt & 1) * (XOFF + WSZ);
        const uint2* Ws = Xs + XOFF;

        #pragma unroll
        for (int kk = 0; kk < 2; kk++) {
            uint2 a0 = Xs[(r0 + g    ) * PXS + 8*kk + tg    ];
            uint2 a1 = Xs[(r0 + g + 8) * PXS + 8*kk + tg    ];
            uint2 a2 = Xs[(r0 + g    ) * PXS + 8*kk + tg + 4];
            uint2 a3 = Xs[(r0 + g + 8) * PXS + 8*kk + tg + 4];
            uint32_t ah[4] = {a0.x, a1.x, a2.x, a3.x};
            uint32_t al[4] = {a0.y, a1.y, a2.y, a3.y};
            #pragma unroll
            for (int n = 0; n < 8; n++) {
                uint2 b0 = Ws[(8*n + g) * PWS + 8*kk + tg    ];
                uint2 b1 = Ws[(8*n + g) * PWS + 8*kk + tg + 4];
                mma16(acc[n], ah, b0.x, b1.x);
                mma16(acc[n], ah, b0.y, b1.y);
                mma16(acc[n], al, b0.x, b1.x);
            }
        }
        __syncthreads();
    }

    // epilogue: bias + scatter (cols n0+8n+2tg, rows m0+r0+g and +8)
    const int hh = n0 >> 6;
    #pragma unroll
    for (int n = 0; n < 8; n++) {
        int col = 8*n + 2*tg;           // 0..63 within head, even
        float b0 = Bv[n0 + col], b1 = Bv[n0 + col + 1];
        #pragma unroll
        for (int half = 0; half < 2; half++) {
            int m = m0 + r0 + g + 8*half;
            int bb = m >> 11, s = m & 2047;
            float v0 = acc[n][2*half + 0] + b0;
            float v1 = acc[n][2*half + 1] + b1;
            int cidx = bb*8 + hh;
            if (pz == 0) {
                g_Qp[((size_t)cidx * SQ + s) * (DH/2) + (col>>1)] =
                    pk_pair(v0 * 0.125f, v1 * 0.125f);
            } else if (pz == 1) {
                g_Kp[((size_t)cidx * SQ + s) * (DH/2) + (col>>1)] = pk_pair(v0, v1);
            } else if (pz == 5) {
                g_Kp[((size_t)(16 + cidx) * SQ + s) * (DH/2) + (col>>1)] = pk_pair(v0, v1);
            } else {
                float* Out = (pz == 2) ? g_V : (pz == 3) ? g_LQ
                           : (pz == 4) ? g_LK1 : g_LV;
                *(float2*)&Out[((size_t)cidx * SQ + s) * DH + col] = make_float2(v0, v1);
            }
        }
    }
}

// ---------------- kernel 5: Gram matrix G = LK1^T LK1 per (b,h) ----------------
__global__ __launch_bounds__(256) void gram_kernel() {
    const int bh = blockIdx.x;
    const float* __restrict__ P = g_LK1 + (size_t)bh * SQ * DH;
    __shared__ float T[32][65];
    const int tid = threadIdx.x;
    const int ty = tid >> 4, tx = tid & 15;

    float acc[4][4];
    #pragma unroll
    for (int i = 0; i < 4; i++)
        #pragma unroll
        for (int j = 0; j < 4; j++) acc[i][j] = 0.f;

    for (int s0 = 0; s0 < SQ; s0 += 32) {
        #pragma unroll
        for (int t = 0; t < 2; t++) {
            int idx = tid + t * 256;
            int r = idx >> 4, c = idx & 15;
            float4 v = *(const float4*)&P[(size_t)(s0 + r) * DH + 4*c];
            T[r][4*c+0] = v.x; T[r][4*c+1] = v.y; T[r][4*c+2] = v.z; T[r][4*c+3] = v.w;
        }
        __syncthreads();
        #pragma unroll 8
        for (int ss = 0; ss < 32; ss++) {
            float a_[4], b_[4];
            #pragma unroll
            for (int i = 0; i < 4; i++) a_[i] = T[ss][4*ty + i];
            #pragma unroll
            for (int j = 0; j < 4; j++) b_[j] = T[ss][4*tx + j];
            #pragma unroll
            for (int i = 0; i < 4; i++)
                #pragma unroll
                for (int j = 0; j < 4; j++) acc[i][j] += a_[i] * b_[j];
        }
        __syncthreads();
    }
    #pragma unroll
    for (int i = 0; i < 4; i++)
        #pragma unroll
        for (int j = 0; j < 4; j++)
            g_Mm[bh*4096 + (4*ty + i)*64 + (4*tx + j)] = acc[i][j];
}

// ---------------- kernel 6: V transpose -> packed [plane][d][spair] ----------------
__global__ __launch_bounds__(256) void vtrans_kernel() {
    const int plane = blockIdx.y;
    const int s0 = blockIdx.x * 64;
    const float* __restrict__ src = (plane < 16)
        ? g_V  + (size_t)plane * SQ * DH
        : g_LV + (size_t)(plane - 16) * SQ * DH;
    __shared__ float T[64][65];
    const int tid = threadIdx.x;
    #pragma unroll
    for (int t = 0; t < 16; t++) {
        int idx = tid + 256*t;
        int sl = idx >> 6, d = idx & 63;
        T[d][sl] = src[(size_t)(s0 + sl) * DH + d];
    }
    __syncthreads();
    uint2* dst = g_Vtp + (size_t)plane * DH * (SQ/2);
    #pragma unroll
    for (int t = 0; t < 8; t++) {
        int idx = tid + 256*t;
        int d = idx >> 5, sp = idx & 31;
        dst[(size_t)d * (SQ/2) + (s0 >> 1) + sp] = pk_pair(T[d][2*sp], T[d][2*sp + 1]);
    }
}

// ---------------- kernel 7: LQ2 = (LQ @ G) * 0.125 -> packed plane 16+bh ----------------
__global__ __launch_bounds__(256) void lqx_kernel() {
    const int bh = blockIdx.y;
    const int r0 = blockIdx.x * 64;
    const float* __restrict__ Qp = g_LQ + (size_t)bh * SQ * DH;
    const float* __restrict__ Mp = g_Mm + bh * 4096;

    __shared__ float Msm[64*65];
    __shared__ float Qt[64*65];

    const int tid = threadIdx.x;

    #pragma unroll
    for (int t = 0; t < 4; t++) {
        int idx = tid + t * 256;
        int r = idx >> 4, c = idx & 15;
        float4 mv = *(const float4*)&Mp[r*64 + 4*c];
        Msm[r*65 + 4*c+0] = mv.x; Msm[r*65 + 4*c+1] = mv.y;
        Msm[r*65 + 4*c+2] = mv.z; Msm[r*65 + 4*c+3] = mv.w;
        float4 qv = *(const float4*)&Qp[(size_t)(r0 + r) * DH + 4*c];
        Qt[r*65 + 4*c+0] = qv.x; Qt[r*65 + 4*c+1] = qv.y;
        Qt[r*65 + 4*c+2] = qv.z; Qt[r*65 + 4*c+3] = qv.w;
    }
    __syncthreads();

    const int ty = tid >> 5;
    const int tx = tid & 31;

    float acc[8][2];
    #pragma unroll
    for (int a = 0; a < 8; a++) { acc[a][0] = 0.f; acc[a][1] = 0.f; }

    #pragma unroll 4
    for (int k = 0; k < 64; k++) {
        float mb0 = Msm[k*65 + 2*tx], mb1 = Msm[k*65 + 2*tx + 1];
        #pragma unroll
        for (int a = 0; a < 8; a++) {
            float qa = Qt[(ty + 8*a)*65 + k];
            acc[a][0] += qa * mb0;
            acc[a][1] += qa * mb1;
        }
    }

    const int plane = 16 + bh;
    #pragma unroll
    for (int a = 0; a < 8; a++) {
        int row = r0 + ty + 8*a;
        g_Qp[((size_t)plane * SQ + row) * (DH/2) + tx] =
            pk_pair(acc[a][0] * 0.125f, acc[a][1] * 0.125f);
    }
}

// ---------------- kernel 8: flash attention, bf16 m16n8k16, BR=128 / 8 warps ----------------
#define KSTR 36   // uint2 per staged row

__global__ __launch_bounds__(256, 1) void flash_bf(const float* __restrict__ mask,
                                                   float* __restrict__ out) {
    extern __shared__ uint2 smem2[];
    uint2* Kb0 = smem2;
    uint2* Kb1 = Kb0 + 64*KSTR;
    uint2* Vb0 = Kb1 + 64*KSTR;
    uint2* Vb1 = Vb0 + 64*KSTR;

    const int rt = blockIdx.x;
    const int plane = blockIdx.y;
    const int branch = plane >> 4;
    const int cidx = plane & 15;
    const int bb = cidx >> 3;
    const int h  = cidx & 7;
    const int ho = branch ? (8 + h) : h;
    const bool domask = (branch == 0);

    const uint2* Qp  = g_Qp  + (size_t)plane * SQ * (DH/2);
    const uint2* Kp  = g_Kp  + (size_t)plane * SQ * (DH/2);
    const uint2* Vtp = g_Vtp + (size_t)plane * DH * (SQ/2);

    const int tid  = threadIdx.x;
    const int lane = tid & 31;
    const int g    = lane >> 2;
    const int tg   = lane & 3;
    const int r0   = 16 * (tid >> 5);

    const uint32_t kb0 = (uint32_t)__cvta_generic_to_shared(Kb0);
    const uint32_t kb1 = (uint32_t)__cvta_generic_to_shared(Kb1);
    const uint32_t vb0 = (uint32_t)__cvta_generic_to_shared(Vb0);
    const uint32_t vb1 = (uint32_t)__cvta_generic_to_shared(Vb1);

    auto stage = [&](int kt, int buf) {
        uint32_t kb = buf ? kb1 : kb0;
        uint32_t vb = buf ? vb1 : vb0;
        #pragma unroll
        for (int t = 0; t < 4; t++) {
            int idx = tid + 256*t;
            int r = idx >> 4, c = idx & 15;
            cp16(kb + (uint32_t)(r*KSTR*8 + c*16),
                 Kp + (size_t)(kt*64 + r) * (DH/2) + 2*c);
            cp16(vb + (uint32_t)(r*KSTR*8 + c*16),
                 Vtp + (size_t)r * (SQ/2) + kt*32 + 2*c);
        }
        asm volatile("cp.async.commit_group;\n");
    };

    uint32_t qh[4][4], ql[4][4];
    #pragma unroll
    for (int kk = 0; kk < 4; kk++) {
        const uint2* qb = Qp + (size_t)(rt*128) * (DH/2);
        uint2 q00 = qb[(size_t)(r0 + g    ) * (DH/2) + 8*kk + tg    ];
        uint2 q10 = qb[(size_t)(r0 + g + 8) * (DH/2) + 8*kk + tg    ];
        uint2 q01 = qb[(size_t)(r0 + g    ) * (DH/2) + 8*kk + tg + 4];
        uint2 q11 = qb[(size_t)(r0 + g + 8) * (DH/2) + 8*kk + tg + 4];
        qh[kk][0] = q00.x; qh[kk][1] = q10.x; qh[kk][2] = q01.x; qh[kk][3] = q11.x;
        ql[kk][0] = q00.y; ql[kk][1] = q10.y; ql[kk][2] = q01.y; ql[kk][3] = q11.y;
    }

    float o[8][4];
    #pragma unroll
    for (int n = 0; n < 8; n++)
        #pragma unroll
        for (int q = 0; q < 4; q++) o[n][q] = 0.f;
    float m0r = -3.0e38f, m1r = -3.0e38f, l0r = 0.f, l1r = 0.f;

    stage(0, 0);

    for (int kt = 0; kt < 32; kt++) {
        if (kt + 1 < 32) {
            stage(kt + 1, (kt + 1) & 1);
            asm volatile("cp.async.wait_group 1;\n");
        } else {
            asm volatile("cp.async.wait_group 0;\n");
        }
        __syncthreads();
        const uint2* Ks = (kt & 1) ? Kb1 : Kb0;
        const uint2* Vs = (kt & 1) ? Vb1 : Vb0;

        float sv[8][4];
        #pragma unroll
        for (int n = 0; n < 8; n++)
            #pragma unroll
            for (int q = 0; q < 4; q++) sv[n][q] = 0.f;

        #pragma unroll
        for (int kk = 0; kk < 4; kk++) {
            #pragma unroll
            for (int n = 0; n < 8; n++) {
                uint2 b0 = Ks[(8*n + g) * KSTR + 8*kk + tg    ];
                uint2 b1 = Ks[(8*n + g) * KSTR + 8*kk + tg + 4];
                mma16(sv[n], qh[kk], b0.x, b1.x);
                mma16(sv[n], qh[kk], b0.y, b1.y);
                mma16(sv[n], ql[kk], b0.x, b1.x);
            }
        }

        if (domask) {
            #pragma unroll
            for (int n = 0; n < 8; n++) {
                float2 mm = __ldg((const float2*)&mask[(size_t)bb * SQ + kt*64 + 8*n + 2*tg]);
                sv[n][0] += mm.x; sv[n][1] += mm.y;
                sv[n][2] += mm.x; sv[n][3] += mm.y;
            }
        }

        float mt0 = sv[0][0], mt1 = sv[0][2];
        #pragma unroll
        for (int n = 0; n < 8; n++) {
            mt0 = fmaxf(mt0, fmaxf(sv[n][0], sv[n][1]));
            mt1 = fmaxf(mt1, fmaxf(sv[n][2], sv[n][3]));
        }
        mt0 = fmaxf(mt0, __shfl_xor_sync(0xffffffffu, mt0, 1));
        mt0 = fmaxf(mt0, __shfl_xor_sync(0xffffffffu, mt0, 2));
        mt1 = fmaxf(mt1, __shfl_xor_sync(0xffffffffu, mt1, 1));
        mt1 = fmaxf(mt1, __shfl_xor_sync(0xffffffffu, mt1, 2));

        float mn0 = fmaxf(m0r, mt0), mn1 = fmaxf(m1r, mt1);
        float c0 = __expf(m0r - mn0), c1 = __expf(m1r - mn1);
        float s0 = 0.f, s1 = 0.f;
        #pragma unroll
        for (int n = 0; n < 8; n++) {
            sv[n][0] = __expf(sv[n][0] - mn0); s0 += sv[n][0];
            sv[n][1] = __expf(sv[n][1] - mn0); s0 += sv[n][1];
            sv[n][2] = __expf(sv[n][2] - mn1); s1 += sv[n][2];
            sv[n][3] = __expf(sv[n][3] - mn1); s1 += sv[n][3];
        }
        s0 += __shfl_xor_sync(0xffffffffu, s0, 1);
        s0 += __shfl_xor_sync(0xffffffffu, s0, 2);
        s1 += __shfl_xor_sync(0xffffffffu, s1, 1);
        s1 += __shfl_xor_sync(0xffffffffu, s1, 2);
        l0r = l0r * c0 + s0; m0r = mn0;
        l1r = l1r * c1 + s1; m1r = mn1;
        #pragma unroll
        for (int n = 0; n < 8; n++) {
            o[n][0] *= c0; o[n][1] *= c0;
            o[n][2] *= c1; o[n][3] *= c1;
        }

        uint32_t php[8][2], plp[8][2];
        #pragma unroll
        for (int n = 0; n < 8; n++) {
            __nv_bfloat16 h0 = __float2bfloat16_rn(sv[n][0]);
            __nv_bfloat16 h1 = __float2bfloat16_rn(sv[n][1]);
            __nv_bfloat16 h2 = __float2bfloat16_rn(sv[n][2]);
            __nv_bfloat16 h3 = __float2bfloat16_rn(sv[n][3]);
            php[n][0] = pk2(h0, h1);
            php[n][1] = pk2(h2, h3);
            float l0 = sv[n][0] - __bfloat162float(h0);
            float l1 = sv[n][1] - __bfloat162float(h1);
            float l2 = sv[n][2] - __bfloat162float(h2);
            float l3 = sv[n][3] - __bfloat162float(h3);
            plp[n][0] = pk2(__float2bfloat16_rn(l0), __float2bfloat16_rn(l1));
            plp[n][1] = pk2(__float2bfloat16_rn(l2), __float2bfloat16_rn(l3));
        }

        #pragma unroll
        for (int c = 0; c < 4; c++) {
            uint32_t ah[4] = { php[2*c][0], php[2*c][1], php[2*c+1][0], php[2*c+1][1] };
            uint32_t al[4] = { plp[2*c][0], plp[2*c][1], plp[2*c+1][0], plp[2*c+1][1] };
            #pragma unroll
            for (int n = 0; n < 8; n++) {
                uint2 b0 = Vs[(8*n + g) * KSTR + 8*c + tg    ];
                uint2 b1 = Vs[(8*n + g) * KSTR + 8*c + tg + 4];
                mma16(o[n], ah, b0.x, b1.x);
                mma16(o[n], ah, b0.y, b1.y);
                mma16(o[n], al, b0.x, b1.x);
            }
        }
        __syncthreads();
    }

    float inv0 = 1.0f / l0r, inv1 = 1.0f / l1r;
    int s0row = rt*128 + r0 + g;
    int s1row = s0row + 8;
    #pragma unroll
    for (int n = 0; n < 8; n++) {
        int col = 8*n + 2*tg;
        *(float2*)&out[(size_t)(bb * SQ + s0row) * HID + ho*64 + col] =
            make_float2(o[n][0] * inv0, o[n][1] * inv0);
        *(float2*)&out[(size_t)(bb * SQ + s1row) * HID + ho*64 + col] =
            make_float2(o[n][2] * inv1, o[n][3] * inv1);
    }
}

// ---------------- host ----------------
extern "C" void kernel_launch(void* const* d_in, const int* in_sizes, int n_in,
                              void* d_out, int out_size) {
    const float* X    = (const float*)d_in[0];
    const float* mask = (const float*)d_in[1];

    ProjW pw;
    pw.w[0] = (const float*)d_in[2];  pw.b[0] = (const float*)d_in[3];   // wq, bq
    pw.w[1] = (const float*)d_in[4];  pw.b[1] = (const float*)d_in[5];   // wk, bk
    pw.w[2] = (const float*)d_in[6];  pw.b[2] = (const float*)d_in[7];   // wv, bv
    pw.w[3] = (const float*)d_in[8];  pw.b[3] = (const float*)d_in[9];   // wlq
    pw.w[4] = (const float*)d_in[10]; pw.b[4] = (const float*)d_in[11];  // wlk1
    pw.w[5] = (const float*)d_in[12]; pw.b[5] = (const float*)d_in[13];  // wlk2
    pw.w[6] = nullptr;                pw.b[6] = nullptr;                 // g_wsum/g_bsum

    sum_lv_weights<<<(HID*512 + 255)/256, 256>>>(
        (const float*)d_in[14], (const float*)d_in[16],
        (const float*)d_in[15], (const float*)d_in[17]);              // 1
    split_x<<<4096*512/256, 256>>>(X);                                // 2
    split_w<<<dim3(8, 16, 7), 256>>>(pw);                             // 3

    const int psmem = 2 * (128*PXS + 64*PWS) * sizeof(uint2);         // 61,440 B
    cudaFuncSetAttribute(proj_bf, cudaFuncAttributeMaxDynamicSharedMemorySize, psmem);
    proj_bf<<<dim3(8, 32, 7), 256, psmem>>>(pw);                      // 4 (ncu slot)

    gram_kernel<<<16, 256>>>();                                       // 5
    vtrans_kernel<<<dim3(32, 32), 256>>>();                           // 6
    lqx_kernel<<<dim3(32, 16), 256>>>();                              // 7

    const int fsmem = 4 * 64 * KSTR * sizeof(uint2);                  // 73,728 B
    cudaFuncSetAttribute(flash_bf, cudaFuncAttributeMaxDynamicSharedMemorySize, fsmem);
    flash_bf<<<dim3(16, 32), 256, fsmem>>>(mask, (float*)d_out);      // 8
}

// round 13
// speedup vs baseline: 1.7850x; 1.0659x over previous
#include <cuda_runtime.h>
#include <cuda_bf16.h>
#include <math.h>
#include <stdint.h>

// Problem constants
#define SQ   2048
#define HID  1024
#define DH   64
#define NHB  16
#define BHSD (NHB*SQ*DH)
#define LOG2E 1.4426950408889634f

// ---------------- scratch (static device memory; no allocation) ----------------
__device__ float g_V   [BHSD];
__device__ float g_LV  [BHSD];
__device__ float g_LQ  [BHSD];
__device__ float g_LK1 [BHSD];
__device__ float g_Mm  [NHB*64*64];
__device__ float g_wsum[HID*512];
__device__ float g_bsum[512];
// packed bf16 hi/lo pairs (.x = hi pair, .y = lo pair), PERMUTED within 8-pair groups
__device__ __align__(16) uint2 g_Qp [32*SQ*(DH/2)];   // [plane][s][dpair']
__device__ __align__(16) uint2 g_Kp [32*SQ*(DH/2)];   // [plane][s][dpair']
__device__ __align__(16) uint2 g_Vtp[32*DH*(SQ/2)];   // [plane][d][spair']
__device__ __align__(16) uint2 g_Xp [4096*512];       // [m][kpair']
__device__ __align__(16) uint2 g_Wtp[7*512*512];      // [pz][n][kpair']

struct ProjW {
    const float* w[7];
    const float* b[7];
};

// ---------------- helpers ----------------
__device__ __forceinline__ void mma16(float c[4], const uint32_t a[4],
                                      uint32_t b0, uint32_t b1) {
    asm volatile(
        "mma.sync.aligned.m16n8k16.row.col.f32.bf16.bf16.f32 "
        "{%0,%1,%2,%3}, {%4,%5,%6,%7}, {%8,%9}, {%0,%1,%2,%3};"
        : "+f"(c[0]), "+f"(c[1]), "+f"(c[2]), "+f"(c[3])
        : "r"(a[0]), "r"(a[1]), "r"(a[2]), "r"(a[3]), "r"(b0), "r"(b1));
}
__device__ __forceinline__ void cp16(uint32_t dst, const void* src) {
    asm volatile("cp.async.cg.shared.global [%0], [%1], 16;\n" :: "r"(dst), "l"(src));
}
__device__ __forceinline__ uint32_t pk2(__nv_bfloat16 a, __nv_bfloat16 b) {
    uint16_t xa = *reinterpret_cast<uint16_t*>(&a);
    uint16_t xb = *reinterpret_cast<uint16_t*>(&b);
    return (uint32_t)xa | ((uint32_t)xb << 16);
}
__device__ __forceinline__ uint2 pk_pair(float v0, float v1) {
    __nv_bfloat16 h0 = __float2bfloat16_rn(v0), h1 = __float2bfloat16_rn(v1);
    float l0 = v0 - __bfloat162float(h0), l1 = v1 - __bfloat162float(h1);
    return make_uint2(pk2(h0, h1),
                      pk2(__float2bfloat16_rn(l0), __float2bfloat16_rn(l1)));
}
// fragment permutation: within each 8-pair group, pair c stored at 2*(c&3)+(c>>2)
__device__ __forceinline__ int pidx(int p) {
    return (p & ~7) | ((p & 3) << 1) | ((p >> 2) & 1);
}
__device__ __forceinline__ float ex2(float x) {
    float r; asm("ex2.approx.ftz.f32 %0, %1;" : "=f"(r) : "f"(x));
    return r;
}

// ---------------- kernel 1: fold wlv1+wlv2 ----------------
__global__ void sum_lv_weights(const float* __restrict__ w1, const float* __restrict__ w2,
                               const float* __restrict__ b1, const float* __restrict__ b2) {
    int i = blockIdx.x * blockDim.x + threadIdx.x;
    if (i < HID*512) g_wsum[i] = w1[i] + w2[i];
    if (i < 512)     g_bsum[i] = b1[i] + b2[i];
}

// ---------------- kernel 2: split X into packed bf16 pairs (permuted) ----------------
__global__ __launch_bounds__(256) void split_x(const float* __restrict__ X) {
    int idx = blockIdx.x * 256 + threadIdx.x;       // pair index (row-major, rows=512 pairs)
    float2 v = *(const float2*)&X[(size_t)idx * 2];
    g_Xp[(idx & ~7) | ((idx & 3) << 1) | ((idx >> 2) & 1)] = pk_pair(v.x, v.y);
}

// ---------------- kernel 3: split + transpose W -> g_Wtp[pz][n][kpair'] ----------------
__global__ __launch_bounds__(256) void split_w(ProjW args) {
    const int pz = blockIdx.z;
    const int n0 = blockIdx.x * 64;
    const int k0 = blockIdx.y * 64;
    const float* __restrict__ W = (pz == 6) ? g_wsum : args.w[pz];

    __shared__ float T[64][65];
    const int tid = threadIdx.x;
    #pragma unroll
    for (int t = 0; t < 16; t++) {
        int idx = tid + 256*t;
        int kk = idx >> 6, nn = idx & 63;
        T[kk][nn] = W[(size_t)(k0 + kk) * 512 + n0 + nn];
    }
    __syncthreads();
    #pragma unroll
    for (int t = 0; t < 8; t++) {
        int idx = tid + 256*t;          // 64n x 32kp
        int nn = idx >> 5, kp = idx & 31;
        g_Wtp[((size_t)pz * 512 + n0 + nn) * 512 + (k0 >> 1) + pidx(kp)] =
            pk_pair(T[2*kp][nn], T[2*kp + 1][nn]);
    }
}

// ---------------- kernel 4: projection GEMM, bf16-pair mma16, LDS.128 fragments ----------------
#define PXS4 12   // uint4 stride for X rows (stride 24 uint2: 48-bank offset/row = 16 mod 32)
#define PWS4 12

__global__ __launch_bounds__(256, 2) void proj_bf(ProjW args) {
    extern __shared__ uint4 psm4[];
    const int XOFF4 = 128*PXS4, WSZ4 = 64*PWS4;    // uint4 counts

    const int pz = blockIdx.z;
    const int n0 = blockIdx.x * 64;
    const int m0 = blockIdx.y * 128;
    const float* __restrict__ Bv = (pz == 6) ? g_bsum : args.b[pz];

    const uint2* __restrict__ Xp  = g_Xp + (size_t)m0 * 512;
    const uint2* __restrict__ Wtp = g_Wtp + ((size_t)pz * 512 + n0) * 512;

    const int tid  = threadIdx.x;
    const int lane = tid & 31;
    const int g    = lane >> 2;
    const int tg   = lane & 3;
    const int r0   = 16 * (tid >> 5);

    const uint32_t sb = (uint32_t)__cvta_generic_to_shared(psm4);

    auto stage = [&](int kt, int buf) {
        uint32_t xb = sb + (uint32_t)(buf * (XOFF4 + WSZ4)) * 16u;
        uint32_t wb = xb + (uint32_t)XOFF4 * 16u;
        #pragma unroll
        for (int t = 0; t < 4; t++) {
            int idx = tid + 256*t;          // 0..1023
            int r = idx >> 3, c = idx & 7;
            cp16(xb + (uint32_t)(r*192 + c*16), Xp + (size_t)r*512 + kt*16 + 2*c);
        }
        #pragma unroll
        for (int t = 0; t < 2; t++) {
            int idx = tid + 256*t;          // 0..511
            int r = idx >> 3, c = idx & 7;
            cp16(wb + (uint32_t)(r*192 + c*16), Wtp + (size_t)r*512 + kt*16 + 2*c);
        }
        asm volatile("cp.async.commit_group;\n");
    };

    float acc[8][4];
    #pragma unroll
    for (int n = 0; n < 8; n++)
        #pragma unroll
        for (int q = 0; q < 4; q++) acc[n][q] = 0.f;

    stage(0, 0);

    for (int kt = 0; kt < 32; kt++) {
        if (kt + 1 < 32) {
            stage(kt + 1, (kt + 1) & 1);
            asm volatile("cp.async.wait_group 1;\n");
        } else {
            asm volatile("cp.async.wait_group 0;\n");
        }
        __syncthreads();
        const uint4* Xs = psm4 + (kt & 1) * (XOFF4 + WSZ4);
        const uint4* Ws = Xs + XOFF4;

        #pragma unroll
        for (int kk = 0; kk < 2; kk++) {
            uint4 u0 = Xs[(r0 + g    ) * PXS4 + 4*kk + tg];
            uint4 u1 = Xs[(r0 + g + 8) * PXS4 + 4*kk + tg];
            uint32_t ah[4] = {u0.x, u1.x, u0.z, u1.z};
            uint32_t al[4] = {u0.y, u1.y, u0.w, u1.w};
            #pragma unroll
            for (int n = 0; n < 8; n++) {
                uint4 B = Ws[(8*n + g) * PWS4 + 4*kk + tg];
                mma16(acc[n], ah, B.x, B.z);
                mma16(acc[n], ah, B.y, B.w);
                mma16(acc[n], al, B.x, B.z);
            }
        }
        __syncthreads();
    }

    // epilogue: bias + scatter
    const int hh = n0 >> 6;
    #pragma unroll
    for (int n = 0; n < 8; n++) {
        int col = 8*n + 2*tg;           // even, 0..63 within head
        float b0 = Bv[n0 + col], b1 = Bv[n0 + col + 1];
        #pragma unroll
        for (int half = 0; half < 2; half++) {
            int m = m0 + r0 + g + 8*half;
            int bb = m >> 11, s = m & 2047;
            float v0 = acc[n][2*half + 0] + b0;
            float v1 = acc[n][2*half + 1] + b1;
            int cidx = bb*8 + hh;
            int pp = pidx(col >> 1);
            if (pz == 0) {
                g_Qp[((size_t)cidx * SQ + s) * (DH/2) + pp] =
                    pk_pair(v0 * (0.125f*LOG2E), v1 * (0.125f*LOG2E));
            } else if (pz == 1) {
                g_Kp[((size_t)cidx * SQ + s) * (DH/2) + pp] = pk_pair(v0, v1);
            } else if (pz == 5) {
                g_Kp[((size_t)(16 + cidx) * SQ + s) * (DH/2) + pp] = pk_pair(v0, v1);
            } else {
                float* Out = (pz == 2) ? g_V : (pz == 3) ? g_LQ
                           : (pz == 4) ? g_LK1 : g_LV;
                *(float2*)&Out[((size_t)cidx * SQ + s) * DH + col] = make_float2(v0, v1);
            }
        }
    }
}

// ---------------- kernel 5: Gram matrix G = LK1^T LK1 per (b,h) ----------------
__global__ __launch_bounds__(256) void gram_kernel() {
    const int bh = blockIdx.x;
    const float* __restrict__ P = g_LK1 + (size_t)bh * SQ * DH;
    __shared__ float T[32][65];
    const int tid = threadIdx.x;
    const int ty = tid >> 4, tx = tid & 15;

    float acc[4][4];
    #pragma unroll
    for (int i = 0; i < 4; i++)
        #pragma unroll
        for (int j = 0; j < 4; j++) acc[i][j] = 0.f;

    for (int s0 = 0; s0 < SQ; s0 += 32) {
        #pragma unroll
        for (int t = 0; t < 2; t++) {
            int idx = tid + t * 256;
            int r = idx >> 4, c = idx & 15;
            float4 v = *(const float4*)&P[(size_t)(s0 + r) * DH + 4*c];
            T[r][4*c+0] = v.x; T[r][4*c+1] = v.y; T[r][4*c+2] = v.z; T[r][4*c+3] = v.w;
        }
        __syncthreads();
        #pragma unroll 8
        for (int ss = 0; ss < 32; ss++) {
            float a_[4], b_[4];
            #pragma unroll
            for (int i = 0; i < 4; i++) a_[i] = T[ss][4*ty + i];
            #pragma unroll
            for (int j = 0; j < 4; j++) b_[j] = T[ss][4*tx + j];
            #pragma unroll
            for (int i = 0; i < 4; i++)
                #pragma unroll
                for (int j = 0; j < 4; j++) acc[i][j] += a_[i] * b_[j];
        }
        __syncthreads();
    }
    #pragma unroll
    for (int i = 0; i < 4; i++)
        #pragma unroll
        for (int j = 0; j < 4; j++)
            g_Mm[bh*4096 + (4*ty + i)*64 + (4*tx + j)] = acc[i][j];
}

// ---------------- kernel 6: V transpose -> packed [plane][d][spair'] ----------------
__global__ __launch_bounds__(256) void vtrans_kernel() {
    const int plane = blockIdx.y;
    const int s0 = blockIdx.x * 64;
    const float* __restrict__ src = (plane < 16)
        ? g_V  + (size_t)plane * SQ * DH
        : g_LV + (size_t)(plane - 16) * SQ * DH;
    __shared__ float T[64][65];
    const int tid = threadIdx.x;
    #pragma unroll
    for (int t = 0; t < 16; t++) {
        int idx = tid + 256*t;
        int sl = idx >> 6, d = idx & 63;
        T[d][sl] = src[(size_t)(s0 + sl) * DH + d];
    }
    __syncthreads();
    uint2* dst = g_Vtp + (size_t)plane * DH * (SQ/2);
    #pragma unroll
    for (int t = 0; t < 8; t++) {
        int idx = tid + 256*t;
        int d = idx >> 5, sp = idx & 31;
        dst[(size_t)d * (SQ/2) + (s0 >> 1) + pidx(sp)] = pk_pair(T[d][2*sp], T[d][2*sp + 1]);
    }
}

// ---------------- kernel 7: LQ2 = (LQ @ G) * 0.125*log2e -> packed plane 16+bh ----------------
__global__ __launch_bounds__(256) void lqx_kernel() {
    const int bh = blockIdx.y;
    const int r0 = blockIdx.x * 64;
    const float* __restrict__ Qp = g_LQ + (size_t)bh * SQ * DH;
    const float* __restrict__ Mp = g_Mm + bh * 4096;

    __shared__ float Msm[64*65];
    __shared__ float Qt[64*65];

    const int tid = threadIdx.x;

    #pragma unroll
    for (int t = 0; t < 4; t++) {
        int idx = tid + t * 256;
        int r = idx >> 4, c = idx & 15;
        float4 mv = *(const float4*)&Mp[r*64 + 4*c];
        Msm[r*65 + 4*c+0] = mv.x; Msm[r*65 + 4*c+1] = mv.y;
        Msm[r*65 + 4*c+2] = mv.z; Msm[r*65 + 4*c+3] = mv.w;
        float4 qv = *(const float4*)&Qp[(size_t)(r0 + r) * DH + 4*c];
        Qt[r*65 + 4*c+0] = qv.x; Qt[r*65 + 4*c+1] = qv.y;
        Qt[r*65 + 4*c+2] = qv.z; Qt[r*65 + 4*c+3] = qv.w;
    }
    __syncthreads();

    const int ty = tid >> 5;
    const int tx = tid & 31;

    float acc[8][2];
    #pragma unroll
    for (int a = 0; a < 8; a++) { acc[a][0] = 0.f; acc[a][1] = 0.f; }

    #pragma unroll 4
    for (int k = 0; k < 64; k++) {
        float mb0 = Msm[k*65 + 2*tx], mb1 = Msm[k*65 + 2*tx + 1];
        #pragma unroll
        for (int a = 0; a < 8; a++) {
            float qa = Qt[(ty + 8*a)*65 + k];
            acc[a][0] += qa * mb0;
            acc[a][1] += qa * mb1;
        }
    }

    const int plane = 16 + bh;
    #pragma unroll
    for (int a = 0; a < 8; a++) {
        int row = r0 + ty + 8*a;
        g_Qp[((size_t)plane * SQ + row) * (DH/2) + pidx(tx)] =
            pk_pair(acc[a][0] * (0.125f*LOG2E), acc[a][1] * (0.125f*LOG2E));
    }
}

// ---------------- kernel 8: flash attention, bf16-pair mma16, LDS.128 fragments ----------------
#define FRS4 20   // uint4 stride per staged row (40 uint2: 80-bank offset/row = 16 mod 32)

__global__ __launch_bounds__(256, 1) void flash_bf(const float* __restrict__ mask,
                                                   float* __restrict__ out) {
    extern __shared__ uint4 smem4[];
    uint4* Kb0 = smem4;                 // 64*FRS4
    uint4* Kb1 = Kb0 + 64*FRS4;
    uint4* Vb0 = Kb1 + 64*FRS4;
    uint4* Vb1 = Vb0 + 64*FRS4;

    const int rt = blockIdx.x;
    const int plane = blockIdx.y;
    const int branch = plane >> 4;
    const int cidx = plane & 15;
    const int bb = cidx >> 3;
    const int h  = cidx & 7;
    const int ho = branch ? (8 + h) : h;
    const bool domask = (branch == 0);

    const uint2* Qp  = g_Qp  + (size_t)plane * SQ * (DH/2);
    const uint2* Kp  = g_Kp  + (size_t)plane * SQ * (DH/2);
    const uint2* Vtp = g_Vtp + (size_t)plane * DH * (SQ/2);

    const int tid  = threadIdx.x;
    const int lane = tid & 31;
    const int g    = lane >> 2;
    const int tg   = lane & 3;
    const int r0   = 16 * (tid >> 5);

    const uint32_t kb0 = (uint32_t)__cvta_generic_to_shared(Kb0);
    const uint32_t kb1 = (uint32_t)__cvta_generic_to_shared(Kb1);
    const uint32_t vb0 = (uint32_t)__cvta_generic_to_shared(Vb0);
    const uint32_t vb1 = (uint32_t)__cvta_generic_to_shared(Vb1);

    auto stage = [&](int kt, int buf) {
        uint32_t kb = buf ? kb1 : kb0;
        uint32_t vb = buf ? vb1 : vb0;
        #pragma unroll
        for (int t = 0; t < 4; t++) {
            int idx = tid + 256*t;          // 0..1023
            int r = idx >> 4, c = idx & 15;
            cp16(kb + (uint32_t)(r*320 + c*16),
                 Kp + (size_t)(kt*64 + r) * (DH/2) + 2*c);
            cp16(vb + (uint32_t)(r*320 + c*16),
                 Vtp + (size_t)r * (SQ/2) + kt*32 + 2*c);
        }
        asm volatile("cp.async.commit_group;\n");
    };

    // ---- Q fragments (permuted packed: uint4 gives hi/lo of tg and tg+4) ----
    uint32_t qh[4][4], ql[4][4];
    {
        const uint4* qb = (const uint4*)(Qp + (size_t)(rt*128) * (DH/2));
        #pragma unroll
        for (int kk = 0; kk < 4; kk++) {
            uint4 u0 = qb[(size_t)(r0 + g    ) * 16 + 4*kk + tg];
            uint4 u1 = qb[(size_t)(r0 + g + 8) * 16 + 4*kk + tg];
            qh[kk][0] = u0.x; qh[kk][1] = u1.x; qh[kk][2] = u0.z; qh[kk][3] = u1.z;
            ql[kk][0] = u0.y; ql[kk][1] = u1.y; ql[kk][2] = u0.w; ql[kk][3] = u1.w;
        }
    }

    float o[8][4];
    #pragma unroll
    for (int n = 0; n < 8; n++)
        #pragma unroll
        for (int q = 0; q < 4; q++) o[n][q] = 0.f;
    float m0r = -3.0e38f, m1r = -3.0e38f, l0r = 0.f, l1r = 0.f;

    stage(0, 0);

    for (int kt = 0; kt < 32; kt++) {
        if (kt + 1 < 32) {
            stage(kt + 1, (kt + 1) & 1);
            asm volatile("cp.async.wait_group 1;\n");
        } else {
            asm volatile("cp.async.wait_group 0;\n");
        }
        __syncthreads();
        const uint4* Ks = (kt & 1) ? Kb1 : Kb0;
        const uint4* Vs = (kt & 1) ? Vb1 : Vb0;

        // ---- S = Q K^T (3-term bf16-pair), scores already in log2 domain ----
        float sv[8][4];
        #pragma unroll
        for (int n = 0; n < 8; n++)
            #pragma unroll
            for (int q = 0; q < 4; q++) sv[n][q] = 0.f;

        #pragma unroll
        for (int kk = 0; kk < 4; kk++) {
            #pragma unroll
            for (int n = 0; n < 8; n++) {
                uint4 B = Ks[(8*n + g) * FRS4 + 4*kk + tg];
                mma16(sv[n], qh[kk], B.x, B.z);
                mma16(sv[n], qh[kk], B.y, B.w);
                mma16(sv[n], ql[kk], B.x, B.z);
            }
        }

        if (domask) {
            #pragma unroll
            for (int n = 0; n < 8; n++) {
                float2 mm = __ldg((const float2*)&mask[(size_t)bb * SQ + kt*64 + 8*n + 2*tg]);
                float a = mm.x * LOG2E, b = mm.y * LOG2E;
                sv[n][0] += a; sv[n][1] += b;
                sv[n][2] += a; sv[n][3] += b;
            }
        }

        // ---- online softmax in base-2 (rows g, g+8; 4-lane groups share a row) ----
        float mt0 = sv[0][0], mt1 = sv[0][2];
        #pragma unroll
        for (int n = 0; n < 8; n++) {
            mt0 = fmaxf(mt0, fmaxf(sv[n][0], sv[n][1]));
            mt1 = fmaxf(mt1, fmaxf(sv[n][2], sv[n][3]));
        }
        mt0 = fmaxf(mt0, __shfl_xor_sync(0xffffffffu, mt0, 1));
        mt0 = fmaxf(mt0, __shfl_xor_sync(0xffffffffu, mt0, 2));
        mt1 = fmaxf(mt1, __shfl_xor_sync(0xffffffffu, mt1, 1));
        mt1 = fmaxf(mt1, __shfl_xor_sync(0xffffffffu, mt1, 2));

        float mn0 = fmaxf(m0r, mt0), mn1 = fmaxf(m1r, mt1);
        float c0 = ex2(m0r - mn0), c1 = ex2(m1r - mn1);
        float s0 = 0.f, s1 = 0.f;
        #pragma unroll
        for (int n = 0; n < 8; n++) {
            sv[n][0] = ex2(sv[n][0] - mn0); s0 += sv[n][0];
            sv[n][1] = ex2(sv[n][1] - mn0); s0 += sv[n][1];
            sv[n][2] = ex2(sv[n][2] - mn1); s1 += sv[n][2];
            sv[n][3] = ex2(sv[n][3] - mn1); s1 += sv[n][3];
        }
        s0 += __shfl_xor_sync(0xffffffffu, s0, 1);
        s0 += __shfl_xor_sync(0xffffffffu, s0, 2);
        s1 += __shfl_xor_sync(0xffffffffu, s1, 1);
        s1 += __shfl_xor_sync(0xffffffffu, s1, 2);
        l0r = l0r * c0 + s0; m0r = mn0;
        l1r = l1r * c1 + s1; m1r = mn1;
        #pragma unroll
        for (int n = 0; n < 8; n++) {
            o[n][0] *= c0; o[n][1] *= c0;
            o[n][2] *= c1; o[n][3] *= c1;
        }

        // ---- pack P into bf16 hi/lo A-fragments (pure local) ----
        uint32_t php[8][2], plp[8][2];
        #pragma unroll
        for (int n = 0; n < 8; n++) {
            __nv_bfloat16 h0 = __float2bfloat16_rn(sv[n][0]);
            __nv_bfloat16 h1 = __float2bfloat16_rn(sv[n][1]);
            __nv_bfloat16 h2 = __float2bfloat16_rn(sv[n][2]);
            __nv_bfloat16 h3 = __float2bfloat16_rn(sv[n][3]);
            php[n][0] = pk2(h0, h1);
            php[n][1] = pk2(h2, h3);
            float l0 = sv[n][0] - __bfloat162float(h0);
            float l1 = sv[n][1] - __bfloat162float(h1);
            float l2 = sv[n][2] - __bfloat162float(h2);
            float l3 = sv[n][3] - __bfloat162float(h3);
            plp[n][0] = pk2(__float2bfloat16_rn(l0), __float2bfloat16_rn(l1));
            plp[n][1] = pk2(__float2bfloat16_rn(l2), __float2bfloat16_rn(l3));
        }

        // ---- O += P V (3-term bf16-pair) ----
        #pragma unroll
        for (int c = 0; c < 4; c++) {
            uint32_t ah[4] = { php[2*c][0], php[2*c][1], php[2*c+1][0], php[2*c+1][1] };
            uint32_t al[4] = { plp[2*c][0], plp[2*c][1], plp[2*c+1][0], plp[2*c+1][1] };
            #pragma unroll
            for (int n = 0; n < 8; n++) {
                uint4 B = Vs[(8*n + g) * FRS4 + 4*c + tg];
                mma16(o[n], ah, B.x, B.z);
                mma16(o[n], ah, B.y, B.w);
                mma16(o[n], al, B.x, B.z);
            }
        }
        __syncthreads();
    }

    // ---- epilogue ----
    float inv0 = 1.0f / l0r, inv1 = 1.0f / l1r;
    int s0row = rt*128 + r0 + g;
    int s1row = s0row + 8;
    #pragma unroll
    for (int n = 0; n < 8; n++) {
        int col = 8*n + 2*tg;
        *(float2*)&out[(size_t)(bb * SQ + s0row) * HID + ho*64 + col] =
            make_float2(o[n][0] * inv0, o[n][1] * inv0);
        *(float2*)&out[(size_t)(bb * SQ + s1row) * HID + ho*64 + col] =
            make_float2(o[n][2] * inv1, o[n][3] * inv1);
    }
}

// ---------------- host ----------------
extern "C" void kernel_launch(void* const* d_in, const int* in_sizes, int n_in,
                              void* d_out, int out_size) {
    const float* X    = (const float*)d_in[0];
    const float* mask = (const float*)d_in[1];

    ProjW pw;
    pw.w[0] = (const float*)d_in[2];  pw.b[0] = (const float*)d_in[3];   // wq, bq
    pw.w[1] = (const float*)d_in[4];  pw.b[1] = (const float*)d_in[5];   // wk, bk
    pw.w[2] = (const float*)d_in[6];  pw.b[2] = (const float*)d_in[7];   // wv, bv
    pw.w[3] = (const float*)d_in[8];  pw.b[3] = (const float*)d_in[9];   // wlq
    pw.w[4] = (const float*)d_in[10]; pw.b[4] = (const float*)d_in[11];  // wlk1
    pw.w[5] = (const float*)d_in[12]; pw.b[5] = (const float*)d_in[13];  // wlk2
    pw.w[6] = nullptr;                pw.b[6] = nullptr;                 // g_wsum/g_bsum

    sum_lv_weights<<<(HID*512 + 255)/256, 256>>>(
        (const float*)d_in[14], (const float*)d_in[16],
        (const float*)d_in[15], (const float*)d_in[17]);              // 1
    split_x<<<4096*512/256, 256>>>(X);                                // 2
    split_w<<<dim3(8, 16, 7), 256>>>(pw);                             // 3

    const int psmem = 2 * (128*PXS4 + 64*PWS4) * sizeof(uint4);       // 73,728 B
    cudaFuncSetAttribute(proj_bf, cudaFuncAttributeMaxDynamicSharedMemorySize, psmem);
    proj_bf<<<dim3(8, 32, 7), 256, psmem>>>(pw);                      // 4 (ncu slot)

    gram_kernel<<<16, 256>>>();                                       // 5
    vtrans_kernel<<<dim3(32, 32), 256>>>();                           // 6
    lqx_kernel<<<dim3(32, 16), 256>>>();                              // 7

    const int fsmem = 4 * 64 * FRS4 * sizeof(uint4);                  // 81,920 B
    cudaFuncSetAttribute(flash_bf, cudaFuncAttributeMaxDynamicSharedMemorySize, fsmem);
    flash_bf<<<dim3(16, 32), 256, fsmem>>>(mask, (float*)d_out);      // 8
}